// round 11
// baseline (speedup 1.0000x reference)
#include <cuda_runtime.h>
#include <math.h>

#define HH 1024
#define WW 1024
#define NPIX (HH * WW)
#define NWORDS (WW / 32)          // 32 packed words per row
#define RPB 8                     // rows per block in kernel A

// kernel B tiling
#define CTILE 32                  // columns per block (one mask word)
#define RTILE 256                 // rows per block
#define HALO  8                   // in-shared scan band beyond the tile
#define SROWS (RTILE + 2 * HALO)  // 272 shared rows
#define NB_C (WW / CTILE)         // 32
#define NB_R (HH / RTILE)         // 4
#define FIXSCALE 1048576.0f       // 2^20 fixed point

// Scratch (no allocations allowed anywhere)
__device__ unsigned int       g_edgebits[2][HH * NWORDS];   // 256 KB
__device__ float              g_g2[2][NPIX];                // 8 MB
__device__ unsigned long long g_acc;   // [63:48] block count, [47:0] fixed-point sum

__device__ __forceinline__ unsigned horiz3(unsigned wv, unsigned wl, unsigned wr) {
    return wv & ((wv << 1) | (wl >> 31)) & ((wv >> 1) | (wr << 31));
}

// ---------------------------------------------------------------------------
// Kernel A: bit-packed edges + per-row 1D distance, RPB rows per block.
// (R6 version verbatim — fastest measured variant.)
// ---------------------------------------------------------------------------
__global__ void __launch_bounds__(WW) edges_rowdist_kernel(
    const float* __restrict__ preds, const float* __restrict__ targets)
{
    const int r0 = blockIdx.x * RPB;
    const int m  = blockIdx.y;
    const int j  = threadIdx.x;
    const float* __restrict__ seg = (m == 0) ? preds : targets;

    // reset the packed accumulator for this replay (stream-ordered before B)
    if (blockIdx.x == 0 && m == 0 && j == 0) g_acc = 0ULL;

    __shared__ unsigned shB[RPB + 2][NWORDS];
    __shared__ unsigned shE[RPB][NWORDS];

    const int t = j >> 5, k = j & 31;

    // load RPB+2 rows (batched for MLP), ballot-pack to bits
    float v[RPB + 2];
    #pragma unroll
    for (int rr = 0; rr < RPB + 2; rr++) {
        const int row = r0 + rr - 1;
        v[rr] = (row >= 0 && row < HH) ? seg[row * WW + j] : 0.0f;
    }
    #pragma unroll
    for (int rr = 0; rr < RPB + 2; rr++) {
        const unsigned b = __ballot_sync(0xffffffffu, v[rr] == 1.0f);
        if (k == 0) shB[rr][t] = b;
    }
    __syncthreads();

    // RPB*NWORDS = 256 threads compute one edge word each
    if (j < RPB * NWORDS) {
        const int w  = j & (NWORDS - 1);
        const int rr = j >> 5;            // NWORDS == 32
        const unsigned hp = horiz3(shB[rr][w],
                                   w > 0 ? shB[rr][w - 1] : 0u,
                                   w < NWORDS - 1 ? shB[rr][w + 1] : 0u);
        const unsigned hc = horiz3(shB[rr + 1][w],
                                   w > 0 ? shB[rr + 1][w - 1] : 0u,
                                   w < NWORDS - 1 ? shB[rr + 1][w + 1] : 0u);
        const unsigned hn = horiz3(shB[rr + 2][w],
                                   w > 0 ? shB[rr + 2][w - 1] : 0u,
                                   w < NWORDS - 1 ? shB[rr + 2][w + 1] : 0u);
        const unsigned e = shB[rr + 1][w] & ~(hp & hc & hn);
        shE[rr][w] = e;
        g_edgebits[m][(r0 + rr) * NWORDS + w] = e;
    }
    __syncthreads();

    // per-pixel nearest edge bit in each of the RPB rows (clz/ffs, exact)
    #pragma unroll
    for (int rr = 0; rr < RPB; rr++) {
        const unsigned ew = shE[rr][t];
        float g;
        if ((ew >> k) & 1u) {
            g = 0.0f;
        } else {
            float dl;
            const unsigned lw = (k > 0) ? (ew & ((1u << k) - 1u)) : 0u;
            if (lw) {
                dl = (float)(k - (31 - __clz(lw)));
            } else {
                int tt = t - 1;
                while (tt >= 0 && shE[rr][tt] == 0u) tt--;
                if (tt >= 0) dl = (float)(j - (tt * 32 + (31 - __clz(shE[rr][tt]))));
                else         dl = (float)j + 1e6f;      // reference default, exact fp32
            }
            float dr;
            const unsigned rw = (k < 31) ? (ew & (0xFFFFFFFEu << k)) : 0u;
            if (rw) {
                dr = (float)(__ffs(rw) - 1 - k);
            } else {
                int tt = t + 1;
                while (tt < NWORDS && shE[rr][tt] == 0u) tt++;
                if (tt < NWORDS) dr = (float)((tt * 32 + (__ffs(shE[rr][tt]) - 1)) - j);
                else             dr = 1e6f - (float)j;  // reference default, exact fp32
            }
            g = fminf(fminf(dl, dr), 1e6f);
        }
        g_g2[m][(r0 + rr) * WW + j] = g * g;
    }
}

// ---------------------------------------------------------------------------
// Kernel B: column lower-envelope in shared tiles (32 cols x 256 rows + 8-row
// halo). float4 staging (4x fewer memory instructions); hot scan loop has NO
// bounds checks (d <= HALO keeps sr+-d in range; OOB rows hold 3e37 which can
// never win). Pixels unresolved at d > HALO (empty-row sentinels / P~2^-200
// interior) take the exact global continuation. Final reduction fused via one
// packed u64 atomic: totally ordered, so the block seeing old_count == N-1
// owns the complete total; integer adds -> bit-deterministic. No fences.
// ---------------------------------------------------------------------------
__global__ void __launch_bounds__(1024) colpass_kernel(float* __restrict__ out)
{
    const int c0 = blockIdx.x * CTILE;
    const int t0 = blockIdx.y * RTILE;
    const int m  = blockIdx.z;

    __shared__ __align__(16) float sh[SROWS][CTILE];
    __shared__ unsigned shM[RTILE];

    const int tid = threadIdx.x;
    const int c   = tid & 31;        // column within tile
    const int rg  = tid >> 5;        // 0..31
    const float* __restrict__ g2 = g_g2[m];

    // float4 staging: SROWS*8 quads, coalesced 128B per shared row
    const int nf4 = SROWS * 8;
    for (int idx = tid; idx < nf4; idx += 1024) {
        const int rr  = idx >> 3;
        const int l4  = idx & 7;
        const int row = t0 - HALO + rr;
        float4 val;
        if (row >= 0 && row < HH) {
            val = *reinterpret_cast<const float4*>(&g2[row * WW + c0 + l4 * 4]);
        } else {
            val = make_float4(3e37f, 3e37f, 3e37f, 3e37f);
        }
        *reinterpret_cast<float4*>(&sh[rr][l4 * 4]) = val;
    }
    if (tid < RTILE)
        shM[tid] = g_edgebits[1 - m][(t0 + tid) * NWORDS + (c0 >> 5)];
    __syncthreads();

    float acc = 0.0f;
    #pragma unroll
    for (int q = 0; q < RTILE / 32; q++) {
        const int rl = rg + 32 * q;          // row within tile
        if ((shM[rl] >> c) & 1u) {
            const int sr = rl + HALO;        // shared row index
            float best = sh[sr][c];
            int d = 1;
            // hot loop: no bounds checks (sr+-d always valid for d <= HALO)
            while (d <= HALO && (float)(d * d) < best) {
                best = fminf(best,
                             fminf(sh[sr - d][c], sh[sr + d][c]) + (float)(d * d));
                d++;
            }
            // rare exact continuation beyond the halo (global memory)
            if ((float)(d * d) < best) {
                const int r = t0 + rl;       // global row
                while ((float)(d * d) < best) {
                    const float vu = (r - d >= 0) ? g2[(r - d) * WW + c0 + c] : 3e37f;
                    const float vd = (r + d < HH) ? g2[(r + d) * WW + c0 + c] : 3e37f;
                    best = fminf(best, fminf(vu, vd) + (float)(d * d));
                    d++;
                    if (r - d < 0 && r + d >= HH) break;
                }
            }
            acc += sqrtf(best);
        }
    }

    // deterministic in-block reduction
    float s = acc;
    #pragma unroll
    for (int o = 16; o > 0; o >>= 1) s += __shfl_down_sync(0xffffffffu, s, o);

    __shared__ float warpsum[32];
    if (c == 0) warpsum[rg] = s;
    __syncthreads();

    if (tid == 0) {
        float w = 0.0f;
        #pragma unroll
        for (int i = 0; i < 32; i++) w += warpsum[i];   // fixed order, deterministic

        const unsigned long long vfix =
            (unsigned long long)__float2ull_rn(w * FIXSCALE);
        const unsigned long long packed = (1ULL << 48) | vfix;
        const unsigned long long old = atomicAdd(&g_acc, packed);

        const int nblocks = NB_C * NB_R * 2;            // 256
        if ((old >> 48) == (unsigned long long)(nblocks - 1)) {
            const unsigned long long total = (old & 0xFFFFFFFFFFFFULL) + vfix;
            const float loss =
                (float)((double)total * (1.0 / (double)FIXSCALE))
                / (2.0f * (float)NPIX);
            out[0] = 1.0f / (1.0f + expf(-loss));
        }
    }
}

// ---------------------------------------------------------------------------
extern "C" void kernel_launch(void* const* d_in, const int* in_sizes, int n_in,
                              void* d_out, int out_size)
{
    const float* preds   = (const float*)d_in[0];
    const float* targets = (const float*)d_in[1];
    float* out = (float*)d_out;
    (void)in_sizes; (void)n_in; (void)out_size;

    dim3 gridA(HH / RPB, 2);
    edges_rowdist_kernel<<<gridA, WW>>>(preds, targets);

    dim3 gridB(NB_C, NB_R, 2);
    colpass_kernel<<<gridB, 1024>>>(out);
}

// round 12
// speedup vs baseline: 1.1045x; 1.1045x over previous
#include <cuda_runtime.h>
#include <math.h>

#define HH 1024
#define WW 1024
#define NPIX (HH * WW)
#define NWORDS (WW / 32)          // 32 packed words per row
#define RPB 8                     // rows per block in kernel A

// kernel B tiling
#define CTILE 32                  // columns per block (one mask word)
#define RTILE 256                 // rows per block
#define HALO  32                  // in-shared scan band beyond the tile
#define SROWS (RTILE + 2 * HALO)  // 320 shared rows
#define NB_C (WW / CTILE)         // 32
#define NB_R (HH / RTILE)         // 4
#define FIXSCALE 1048576.0f       // 2^20 fixed point
#define LUTN 2048                 // sqrt LUT entries (covers best <= 2047)

// Scratch (no allocations allowed anywhere)
__device__ unsigned int       g_edgebits[2][HH * NWORDS];   // 256 KB
__device__ float              g_g2[2][NPIX];                // 8 MB
__device__ unsigned long long g_acc;   // [63:48] block count, [47:0] fixed-point sum

__device__ __forceinline__ unsigned horiz3(unsigned wv, unsigned wl, unsigned wr) {
    return wv & ((wv << 1) | (wl >> 31)) & ((wv >> 1) | (wr << 31));
}

// ---------------------------------------------------------------------------
// Kernel A: bit-packed edges + per-row 1D distance, RPB rows per block.
// (R6/R10 version verbatim — fastest measured variant.)
// ---------------------------------------------------------------------------
__global__ void __launch_bounds__(WW) edges_rowdist_kernel(
    const float* __restrict__ preds, const float* __restrict__ targets)
{
    const int r0 = blockIdx.x * RPB;
    const int m  = blockIdx.y;
    const int j  = threadIdx.x;
    const float* __restrict__ seg = (m == 0) ? preds : targets;

    // reset the packed accumulator for this replay (stream-ordered before B)
    if (blockIdx.x == 0 && m == 0 && j == 0) g_acc = 0ULL;

    __shared__ unsigned shB[RPB + 2][NWORDS];
    __shared__ unsigned shE[RPB][NWORDS];

    const int t = j >> 5, k = j & 31;

    // load RPB+2 rows (batched for MLP), ballot-pack to bits
    float v[RPB + 2];
    #pragma unroll
    for (int rr = 0; rr < RPB + 2; rr++) {
        const int row = r0 + rr - 1;
        v[rr] = (row >= 0 && row < HH) ? seg[row * WW + j] : 0.0f;
    }
    #pragma unroll
    for (int rr = 0; rr < RPB + 2; rr++) {
        const unsigned b = __ballot_sync(0xffffffffu, v[rr] == 1.0f);
        if (k == 0) shB[rr][t] = b;
    }
    __syncthreads();

    // RPB*NWORDS = 256 threads compute one edge word each
    if (j < RPB * NWORDS) {
        const int w  = j & (NWORDS - 1);
        const int rr = j >> 5;            // NWORDS == 32
        const unsigned hp = horiz3(shB[rr][w],
                                   w > 0 ? shB[rr][w - 1] : 0u,
                                   w < NWORDS - 1 ? shB[rr][w + 1] : 0u);
        const unsigned hc = horiz3(shB[rr + 1][w],
                                   w > 0 ? shB[rr + 1][w - 1] : 0u,
                                   w < NWORDS - 1 ? shB[rr + 1][w + 1] : 0u);
        const unsigned hn = horiz3(shB[rr + 2][w],
                                   w > 0 ? shB[rr + 2][w - 1] : 0u,
                                   w < NWORDS - 1 ? shB[rr + 2][w + 1] : 0u);
        const unsigned e = shB[rr + 1][w] & ~(hp & hc & hn);
        shE[rr][w] = e;
        g_edgebits[m][(r0 + rr) * NWORDS + w] = e;
    }
    __syncthreads();

    // per-pixel nearest edge bit in each of the RPB rows (clz/ffs, exact)
    #pragma unroll
    for (int rr = 0; rr < RPB; rr++) {
        const unsigned ew = shE[rr][t];
        float g;
        if ((ew >> k) & 1u) {
            g = 0.0f;
        } else {
            float dl;
            const unsigned lw = (k > 0) ? (ew & ((1u << k) - 1u)) : 0u;
            if (lw) {
                dl = (float)(k - (31 - __clz(lw)));
            } else {
                int tt = t - 1;
                while (tt >= 0 && shE[rr][tt] == 0u) tt--;
                if (tt >= 0) dl = (float)(j - (tt * 32 + (31 - __clz(shE[rr][tt]))));
                else         dl = (float)j + 1e6f;      // reference default, exact fp32
            }
            float dr;
            const unsigned rw = (k < 31) ? (ew & (0xFFFFFFFEu << k)) : 0u;
            if (rw) {
                dr = (float)(__ffs(rw) - 1 - k);
            } else {
                int tt = t + 1;
                while (tt < NWORDS && shE[rr][tt] == 0u) tt++;
                if (tt < NWORDS) dr = (float)((tt * 32 + (__ffs(shE[rr][tt]) - 1)) - j);
                else             dr = 1e6f - (float)j;  // reference default, exact fp32
            }
            g = fminf(fminf(dl, dr), 1e6f);
        }
        g_g2[m][(r0 + rr) * WW + j] = g * g;
    }
}

// ---------------------------------------------------------------------------
// Kernel B: column lower-envelope in shared tiles (R10 loop verbatim), with
// sqrtf replaced by a shared LUT: hot-path best is always an exact small
// integer in fp32 (candidates are sums of integer squares; fmin preserves
// integrality), so lut[(int)best] == sqrtf(best) BIT-IDENTICALLY (the LUT is
// filled by the same IEEE sqrtf). best >= LUTN (defaults ~1e12, never in
// practice) falls back to sqrtf. Kills the ~1M MUFU sqrt sequences that were
// the kernel's hidden bottleneck. Final reduction fused via one packed u64
// atomic (totally ordered -> last block owns the exact total; deterministic).
// ---------------------------------------------------------------------------
__global__ void __launch_bounds__(1024) colpass_kernel(float* __restrict__ out)
{
    const int c0 = blockIdx.x * CTILE;
    const int t0 = blockIdx.y * RTILE;
    const int m  = blockIdx.z;

    __shared__ float    sh[SROWS][CTILE];
    __shared__ unsigned shM[RTILE];
    __shared__ float    lutSqrt[LUTN];

    const int tid = threadIdx.x;
    const int c   = tid & 31;        // column within tile
    const int rg  = tid >> 5;        // 0..31
    const float* __restrict__ g2 = g_g2[m];

    // sqrt LUT: 2 entries per thread, same IEEE sqrtf as the fallback
    #pragma unroll
    for (int idx = tid; idx < LUTN; idx += 1024)
        lutSqrt[idx] = sqrtf((float)idx);

    // stage g2 tile + halo (coalesced: each warp loads one 128B row stripe)
    #pragma unroll
    for (int rr = rg; rr < SROWS; rr += 32) {
        const int row = t0 - HALO + rr;
        sh[rr][c] = (row >= 0 && row < HH) ? g2[row * WW + c0 + c] : 3e37f;
    }
    if (tid < RTILE)
        shM[tid] = g_edgebits[1 - m][(t0 + tid) * NWORDS + (c0 >> 5)];
    __syncthreads();

    float acc = 0.0f;
    #pragma unroll
    for (int q = 0; q < RTILE / 32; q++) {
        const int rl = rg + 32 * q;          // row within tile
        if ((shM[rl] >> c) & 1u) {
            const int r  = t0 + rl;          // global row
            const int sr = rl + HALO;        // shared row index
            float best = sh[sr][c];
            int d = 1;
            while ((float)(d * d) < best) {  // exact prune
                const float vu = (sr - d >= 0)
                    ? sh[sr - d][c]
                    : ((r - d >= 0) ? g2[(r - d) * WW + c0 + c] : 3e37f);
                const float vd = (sr + d < SROWS)
                    ? sh[sr + d][c]
                    : ((r + d < HH) ? g2[(r + d) * WW + c0 + c] : 3e37f);
                best = fminf(best, fminf(vu, vd) + (float)(d * d));
                d++;
                if (r - d < 0 && r + d >= HH) break;
            }
            // best < LUTN  => best is an exact integer -> LUT == sqrtf(best)
            acc += (best < (float)LUTN) ? lutSqrt[(int)best] : sqrtf(best);
        }
    }

    // deterministic in-block reduction
    float s = acc;
    #pragma unroll
    for (int o = 16; o > 0; o >>= 1) s += __shfl_down_sync(0xffffffffu, s, o);

    __shared__ float warpsum[32];
    if (c == 0) warpsum[rg] = s;
    __syncthreads();

    if (tid == 0) {
        float w = 0.0f;
        #pragma unroll
        for (int i = 0; i < 32; i++) w += warpsum[i];   // fixed order, deterministic

        const unsigned long long vfix =
            (unsigned long long)__float2ull_rn(w * FIXSCALE);
        const unsigned long long packed = (1ULL << 48) | vfix;
        const unsigned long long old = atomicAdd(&g_acc, packed);

        const int nblocks = NB_C * NB_R * 2;            // 256
        if ((old >> 48) == (unsigned long long)(nblocks - 1)) {
            const unsigned long long total = (old & 0xFFFFFFFFFFFFULL) + vfix;
            const float loss =
                (float)((double)total * (1.0 / (double)FIXSCALE))
                / (2.0f * (float)NPIX);
            out[0] = 1.0f / (1.0f + expf(-loss));
        }
    }
}

// ---------------------------------------------------------------------------
extern "C" void kernel_launch(void* const* d_in, const int* in_sizes, int n_in,
                              void* d_out, int out_size)
{
    const float* preds   = (const float*)d_in[0];
    const float* targets = (const float*)d_in[1];
    float* out = (float*)d_out;
    (void)in_sizes; (void)n_in; (void)out_size;

    dim3 gridA(HH / RPB, 2);
    edges_rowdist_kernel<<<gridA, WW>>>(preds, targets);

    dim3 gridB(NB_C, NB_R, 2);
    colpass_kernel<<<gridB, 1024>>>(out);
}

// round 13
// speedup vs baseline: 1.1212x; 1.0152x over previous
#include <cuda_runtime.h>
#include <math.h>

#define HH 1024
#define WW 1024
#define NPIX (HH * WW)
#define NWORDS (WW / 32)          // 32 packed words per row
#define RPB 8                     // rows per block in kernel A

// kernel B tiling
#define CTILE 32                  // columns per block (one mask word)
#define RTILE 256                 // rows per block
#define HALO  32                  // in-shared scan band beyond the tile
#define SROWS (RTILE + 2 * HALO)  // 320 shared rows
#define NB_C (WW / CTILE)         // 32
#define NB_R (HH / RTILE)         // 4
#define FIXSCALE 1048576.0f       // 2^20 fixed point
#define LUTN 2048                 // sqrt LUT entries (covers best <= 2047)

// Scratch (no allocations allowed anywhere)
__device__ unsigned int       g_edgebits[2][HH * NWORDS];   // 256 KB
__device__ float              g_g2[2][NPIX];                // 8 MB
__device__ unsigned long long g_acc;   // [63:48] block count, [47:0] fixed-point sum

__device__ __forceinline__ unsigned horiz3(unsigned wv, unsigned wl, unsigned wr) {
    return wv & ((wv << 1) | (wl >> 31)) & ((wv >> 1) | (wr << 31));
}

// ---------------------------------------------------------------------------
// Kernel A: bit-packed edges + per-row 1D distance, RPB rows per block.
// (R6/R10 version verbatim — fastest measured variant.)
// ---------------------------------------------------------------------------
__global__ void __launch_bounds__(WW) edges_rowdist_kernel(
    const float* __restrict__ preds, const float* __restrict__ targets)
{
    const int r0 = blockIdx.x * RPB;
    const int m  = blockIdx.y;
    const int j  = threadIdx.x;
    const float* __restrict__ seg = (m == 0) ? preds : targets;

    // reset the packed accumulator for this replay (stream-ordered before B)
    if (blockIdx.x == 0 && m == 0 && j == 0) g_acc = 0ULL;

    __shared__ unsigned shB[RPB + 2][NWORDS];
    __shared__ unsigned shE[RPB][NWORDS];

    const int t = j >> 5, k = j & 31;

    // load RPB+2 rows (batched for MLP), ballot-pack to bits
    float v[RPB + 2];
    #pragma unroll
    for (int rr = 0; rr < RPB + 2; rr++) {
        const int row = r0 + rr - 1;
        v[rr] = (row >= 0 && row < HH) ? seg[row * WW + j] : 0.0f;
    }
    #pragma unroll
    for (int rr = 0; rr < RPB + 2; rr++) {
        const unsigned b = __ballot_sync(0xffffffffu, v[rr] == 1.0f);
        if (k == 0) shB[rr][t] = b;
    }
    __syncthreads();

    // RPB*NWORDS = 256 threads compute one edge word each
    if (j < RPB * NWORDS) {
        const int w  = j & (NWORDS - 1);
        const int rr = j >> 5;            // NWORDS == 32
        const unsigned hp = horiz3(shB[rr][w],
                                   w > 0 ? shB[rr][w - 1] : 0u,
                                   w < NWORDS - 1 ? shB[rr][w + 1] : 0u);
        const unsigned hc = horiz3(shB[rr + 1][w],
                                   w > 0 ? shB[rr + 1][w - 1] : 0u,
                                   w < NWORDS - 1 ? shB[rr + 1][w + 1] : 0u);
        const unsigned hn = horiz3(shB[rr + 2][w],
                                   w > 0 ? shB[rr + 2][w - 1] : 0u,
                                   w < NWORDS - 1 ? shB[rr + 2][w + 1] : 0u);
        const unsigned e = shB[rr + 1][w] & ~(hp & hc & hn);
        shE[rr][w] = e;
        g_edgebits[m][(r0 + rr) * NWORDS + w] = e;
    }
    __syncthreads();

    // per-pixel nearest edge bit in each of the RPB rows (clz/ffs, exact)
    #pragma unroll
    for (int rr = 0; rr < RPB; rr++) {
        const unsigned ew = shE[rr][t];
        float g;
        if ((ew >> k) & 1u) {
            g = 0.0f;
        } else {
            float dl;
            const unsigned lw = (k > 0) ? (ew & ((1u << k) - 1u)) : 0u;
            if (lw) {
                dl = (float)(k - (31 - __clz(lw)));
            } else {
                int tt = t - 1;
                while (tt >= 0 && shE[rr][tt] == 0u) tt--;
                if (tt >= 0) dl = (float)(j - (tt * 32 + (31 - __clz(shE[rr][tt]))));
                else         dl = (float)j + 1e6f;      // reference default, exact fp32
            }
            float dr;
            const unsigned rw = (k < 31) ? (ew & (0xFFFFFFFEu << k)) : 0u;
            if (rw) {
                dr = (float)(__ffs(rw) - 1 - k);
            } else {
                int tt = t + 1;
                while (tt < NWORDS && shE[rr][tt] == 0u) tt++;
                if (tt < NWORDS) dr = (float)((tt * 32 + (__ffs(shE[rr][tt]) - 1)) - j);
                else             dr = 1e6f - (float)j;  // reference default, exact fp32
            }
            g = fminf(fminf(dl, dr), 1e6f);
        }
        g_g2[m][(r0 + rr) * WW + j] = g * g;
    }
}

// ---------------------------------------------------------------------------
// Kernel B: column lower-envelope in shared tiles.
// Hot path is a BRANCH-FREE depth-1 sweep:
//   best = min(g2[r], min(g2[r-1], g2[r+1]) + 1)       (3 LDS, no bounds)
// All d>=2 candidates are >= 4, so best <= 4 proves global optimality (g2>=0).
// Unresolved masked lanes (P ~ 0.5%: sparse columns / sentinels) take the
// exact serial continuation from d=2 behind a single __any_sync guard.
// sqrt via shared LUT (bit-identical: hot-path best is an exact integer and
// the LUT is filled by the same IEEE sqrtf; >= LUTN falls back to sqrtf).
// Final reduction fused via one packed u64 atomic (totally ordered -> the
// block seeing old_count == N-1 owns the exact total; integer adds ->
// bit-deterministic; no fences).
// ---------------------------------------------------------------------------
__global__ void __launch_bounds__(1024) colpass_kernel(float* __restrict__ out)
{
    const int c0 = blockIdx.x * CTILE;
    const int t0 = blockIdx.y * RTILE;
    const int m  = blockIdx.z;

    __shared__ float    sh[SROWS][CTILE];
    __shared__ unsigned shM[RTILE];
    __shared__ float    lutSqrt[LUTN];

    const int tid = threadIdx.x;
    const int c   = tid & 31;        // column within tile
    const int rg  = tid >> 5;        // 0..31
    const float* __restrict__ g2 = g_g2[m];

    // sqrt LUT: 2 entries per thread, same IEEE sqrtf as the fallback
    #pragma unroll
    for (int idx = tid; idx < LUTN; idx += 1024)
        lutSqrt[idx] = sqrtf((float)idx);

    // stage g2 tile + halo (coalesced: each warp loads one 128B row stripe)
    #pragma unroll
    for (int rr = rg; rr < SROWS; rr += 32) {
        const int row = t0 - HALO + rr;
        sh[rr][c] = (row >= 0 && row < HH) ? g2[row * WW + c0 + c] : 3e37f;
    }
    if (tid < RTILE)
        shM[tid] = g_edgebits[1 - m][(t0 + tid) * NWORDS + (c0 >> 5)];
    __syncthreads();

    float acc = 0.0f;
    #pragma unroll
    for (int q = 0; q < RTILE / 32; q++) {
        const int rl = rg + 32 * q;          // row within tile
        const int sr = rl + HALO;            // shared row index (HALO..HALO+RTILE-1)
        const unsigned mbit = (shM[rl] >> c) & 1u;

        // branch-free depth-1 sweep (sr±1 always in range; HALO >= 1)
        float best = fminf(sh[sr][c],
                           fminf(sh[sr - 1][c], sh[sr + 1][c]) + 1.0f);

        // rare exact continuation: only when a masked lane is unresolved
        if (__any_sync(0xffffffffu, mbit && (4.0f < best))) {
            if (mbit && (4.0f < best)) {
                const int r = t0 + rl;       // global row
                int d = 2;
                while ((float)(d * d) < best) {
                    const float vu = (sr - d >= 0)
                        ? sh[sr - d][c]
                        : ((r - d >= 0) ? g2[(r - d) * WW + c0 + c] : 3e37f);
                    const float vd = (sr + d < SROWS)
                        ? sh[sr + d][c]
                        : ((r + d < HH) ? g2[(r + d) * WW + c0 + c] : 3e37f);
                    best = fminf(best, fminf(vu, vd) + (float)(d * d));
                    d++;
                    if (r - d < 0 && r + d >= HH) break;
                }
            }
        }

        if (mbit)
            acc += (best < (float)LUTN) ? lutSqrt[(int)best] : sqrtf(best);
    }

    // deterministic in-block reduction
    float s = acc;
    #pragma unroll
    for (int o = 16; o > 0; o >>= 1) s += __shfl_down_sync(0xffffffffu, s, o);

    __shared__ float warpsum[32];
    if (c == 0) warpsum[rg] = s;
    __syncthreads();

    if (tid == 0) {
        float w = 0.0f;
        #pragma unroll
        for (int i = 0; i < 32; i++) w += warpsum[i];   // fixed order, deterministic

        const unsigned long long vfix =
            (unsigned long long)__float2ull_rn(w * FIXSCALE);
        const unsigned long long packed = (1ULL << 48) | vfix;
        const unsigned long long old = atomicAdd(&g_acc, packed);

        const int nblocks = NB_C * NB_R * 2;            // 256
        if ((old >> 48) == (unsigned long long)(nblocks - 1)) {
            const unsigned long long total = (old & 0xFFFFFFFFFFFFULL) + vfix;
            const float loss =
                (float)((double)total * (1.0 / (double)FIXSCALE))
                / (2.0f * (float)NPIX);
            out[0] = 1.0f / (1.0f + expf(-loss));
        }
    }
}

// ---------------------------------------------------------------------------
extern "C" void kernel_launch(void* const* d_in, const int* in_sizes, int n_in,
                              void* d_out, int out_size)
{
    const float* preds   = (const float*)d_in[0];
    const float* targets = (const float*)d_in[1];
    float* out = (float*)d_out;
    (void)in_sizes; (void)n_in; (void)out_size;

    dim3 gridA(HH / RPB, 2);
    edges_rowdist_kernel<<<gridA, WW>>>(preds, targets);

    dim3 gridB(NB_C, NB_R, 2);
    colpass_kernel<<<gridB, 1024>>>(out);
}